// round 10
// baseline (speedup 1.0000x reference)
#include <cuda_runtime.h>
#include <cuda_fp16.h>
#include <cstdint>

// KSparseAutoencoder: B=4096, D=1024, L=16384, K=64, fp32 in/out.
// R10: R6's proven GEMM mainloop (2 CTA/SM, 4-stage cp.async, 474us) with a
// zero-register-cost filter epilogue: count (smem atomics) -> reserve (one
// global atomic per CTA-row) -> write (smem cursor + direct global store).
// Dense activations never touch memory. Topk runs on ~373-entry candidate
// lists with fp64 band refinement + exact fp32 recompute of selected values.

#define BB 4096
#define DD 1024
#define LL 16384
#define KK 64
#define KTOT 1024
#define DELTA 4e-3f
#define TSEL 1.8f
#define CAP 1024

__device__ float g_xbar[(size_t)BB * DD];        // 16 MB exact
__device__ __half g_A2[(size_t)BB * KTOT];       // 8 MB  xhi
__device__ __half g_B2[(size_t)LL * KTOT];       // 32 MB Whi
__device__ float g_WdecT[(size_t)LL * DD];       // 64 MB
__device__ unsigned long long g_cand[(size_t)BB * CAP];  // 32 MB
__device__ int   g_cnt[BB];
__device__ float g_tv[BB * KK];
__device__ int   g_ti[BB * KK];

// ==================== helpers ====================
__device__ __forceinline__ uint32_t smem_u32(const void* p) {
    uint32_t a;
    asm("{ .reg .u64 t; cvta.to.shared.u64 t, %1; cvt.u32.u64 %0, t; }" : "=r"(a) : "l"(p));
    return a;
}
__device__ __forceinline__ void cp16(uint32_t dst, const void* src) {
    asm volatile("cp.async.cg.shared.global [%0], [%1], 16;" :: "r"(dst), "l"(src));
}
__device__ __forceinline__ void cp_commit() { asm volatile("cp.async.commit_group;"); }
__device__ __forceinline__ void cp_wait2()  { asm volatile("cp.async.wait_group 2;" ::: "memory"); }

__device__ __forceinline__ void ldsm_x4(uint32_t* r, uint32_t addr) {
    asm volatile("ldmatrix.sync.aligned.m8n8.x4.shared.b16 {%0,%1,%2,%3}, [%4];"
                 : "=r"(r[0]), "=r"(r[1]), "=r"(r[2]), "=r"(r[3]) : "r"(addr));
}
__device__ __forceinline__ void mma16816(float* c, const uint32_t* a, uint32_t b0, uint32_t b1) {
    asm volatile("mma.sync.aligned.m16n8k16.row.col.f32.f16.f16.f32 "
                 "{%0,%1,%2,%3}, {%4,%5,%6,%7}, {%8,%9}, {%0,%1,%2,%3};"
                 : "+f"(c[0]), "+f"(c[1]), "+f"(c[2]), "+f"(c[3])
                 : "r"(a[0]), "r"(a[1]), "r"(a[2]), "r"(a[3]), "r"(b0), "r"(b1));
}
__device__ __forceinline__ unsigned long long mk_key(float v, int i) {
    unsigned u = __float_as_uint(v);
    u = (u & 0x80000000u) ? ~u : (u | 0x80000000u);
    return ((unsigned long long)u << 32) | (unsigned long long)(0xFFFFFFFFu - (unsigned)i);
}
__device__ __forceinline__ float key_val(unsigned long long kk) {
    unsigned u = (unsigned)(kk >> 32);
    unsigned bits = (u & 0x80000000u) ? (u & 0x7FFFFFFFu) : ~u;
    return __uint_as_float(bits);
}
__device__ __forceinline__ int key_idx(unsigned long long kk) {
    return (int)(0xFFFFFFFFu - (unsigned)(kk & 0xFFFFFFFFu));
}

// ==================== prep kernels ====================
__global__ void k_zero_cnt() {
    int i = blockIdx.x * blockDim.x + threadIdx.x;
    if (i < BB) g_cnt[i] = 0;
}

__global__ void k_prep_a(const float* __restrict__ x, const float* __restrict__ bd) {
    int i = blockIdx.x * blockDim.x + threadIdx.x;
    if (i >= BB * DD) return;
    int d = i & (DD - 1);
    float xb = x[i] - bd[d];
    g_xbar[i] = xb;
    g_A2[i] = __float2half_rn(xb);
}

__global__ void k_prep_b(const float* __restrict__ W) {
    int i = blockIdx.x * blockDim.x + threadIdx.x;
    if (i >= LL * DD) return;
    g_B2[i] = __float2half_rn(W[i]);
}

// ---------------- transpose W_dec [D][L] -> WdecT [L][D] ----------------
__global__ void k_transpose(const float* __restrict__ W) {
    __shared__ float tile[32][33];
    int lx = blockIdx.x * 32 + threadIdx.x;
    int dy = blockIdx.y * 32 + threadIdx.y;
#pragma unroll
    for (int j = 0; j < 32; j += 8)
        tile[threadIdx.y + j][threadIdx.x] = W[(size_t)(dy + j) * LL + lx];
    __syncthreads();
    int dx = blockIdx.y * 32 + threadIdx.x;
    int ly = blockIdx.x * 32 + threadIdx.y;
#pragma unroll
    for (int j = 0; j < 32; j += 8)
        g_WdecT[(size_t)(ly + j) * DD + dx] = tile[threadIdx.x][threadIdx.y + j];
}

// ==================== fp16 mma.sync GEMM (K=1024) + filter epilogue ====================
#define GM 128
#define GN 128
#define GK 32
#define NSTG 32
#define ROWB 80
#define A_BYTES (GM * ROWB)
#define B_BYTES (GN * ROWB)
#define STG_BYTES (A_BYTES + B_BYTES)
#define NPIPE 4
#define GSMEM (NPIPE * STG_BYTES)     // 81920

__global__ __launch_bounds__(256, 2)
void k_gemm(const float* __restrict__ be) {
    extern __shared__ __align__(128) char smem[];
    __shared__ int sCnt[GM];
    __shared__ int sCur[GM];
    const uint32_t sb = smem_u32(smem);
    const int tid = threadIdx.x;
    const int lane = tid & 31;
    const int wid = tid >> 5;
    const int wm = wid >> 2;
    const int wn = wid & 3;
    const int m0 = blockIdx.x * GM;
    const int n0 = blockIdx.y * GN;

    const __half* Ag = g_A2 + (size_t)m0 * KTOT;
    const __half* Bg = g_B2 + (size_t)n0 * KTOT;

    if (tid < GM) sCnt[tid] = 0;

    const int lrow = tid >> 1;
    const int lseg2 = (tid & 1) * 2;
    auto load_stage = [&](int s, int buf) {
        uint32_t ab = sb + buf * STG_BYTES;
        uint32_t bb = ab + A_BYTES;
        const __half* Ak = Ag + s * GK;
        const __half* Bk = Bg + s * GK;
#pragma unroll
        for (int q = 0; q < 2; q++) {
            int seg = lseg2 + q;
            cp16(ab + lrow * ROWB + seg * 16, Ak + (size_t)lrow * KTOT + seg * 8);
            cp16(bb + lrow * ROWB + seg * 16, Bk + (size_t)lrow * KTOT + seg * 8);
        }
        cp_commit();
    };

    float acc[4][4][4];
#pragma unroll
    for (int i = 0; i < 4; i++)
#pragma unroll
        for (int j = 0; j < 4; j++)
#pragma unroll
            for (int q = 0; q < 4; q++) acc[i][j][q] = 0.f;

    load_stage(0, 0);
    load_stage(1, 1);
    load_stage(2, 2);

    const int wm64 = wm * 64;
    const int wn32 = wn * 32;
    const uint32_t a_sub = (uint32_t)(wm64 + (lane & 15)) * ROWB + (((lane >> 4) << 3) << 1);
    const uint32_t b_sub = (uint32_t)(wn32 + (lane & 7) + ((lane & 16) >> 1)) * ROWB
                           + ((lane & 8) << 1);

    for (int s = 0; s < NSTG; s++) {
        const int buf = s & (NPIPE - 1);
        cp_wait2();
        __syncthreads();
        if (s + 3 < NSTG) load_stage(s + 3, (s + 3) & (NPIPE - 1));

        uint32_t ab = sb + buf * STG_BYTES;
        uint32_t bb = ab + A_BYTES;
#pragma unroll
        for (int ks = 0; ks < 2; ks++) {
            const uint32_t k0b = ks * 32;
            uint32_t ra[4][4], rb[2][4];
#pragma unroll
            for (int mt = 0; mt < 4; mt++)
                ldsm_x4(ra[mt], ab + a_sub + (uint32_t)(mt * 16) * ROWB + k0b);
#pragma unroll
            for (int g = 0; g < 2; g++)
                ldsm_x4(rb[g], bb + b_sub + (uint32_t)(g * 16) * ROWB + k0b);
#pragma unroll
            for (int mt = 0; mt < 4; mt++)
#pragma unroll
                for (int nt = 0; nt < 4; nt++)
                    mma16816(acc[mt][nt], ra[mt], rb[nt >> 1][(nt & 1) * 2],
                             rb[nt >> 1][(nt & 1) * 2 + 1]);
        }
    }
    __syncthreads();      // sCnt init visible; mainloop done

    // ---- filter epilogue: count -> reserve -> write ----
    const int cq = (lane & 3) * 2;
    const int rq = lane >> 2;

    // pass 1: count per local row
#pragma unroll
    for (int nt = 0; nt < 4; nt++) {
        const int col = n0 + wn32 + nt * 8 + cq;
        const float2 bev = *(const float2*)(be + col);
#pragma unroll
        for (int mt = 0; mt < 4; mt++) {
            const int lr = wm64 + mt * 16 + rq;
            if (acc[mt][nt][0] + bev.x > TSEL) atomicAdd(&sCnt[lr], 1);
            if (acc[mt][nt][1] + bev.y > TSEL) atomicAdd(&sCnt[lr], 1);
            if (acc[mt][nt][2] + bev.x > TSEL) atomicAdd(&sCnt[lr + 8], 1);
            if (acc[mt][nt][3] + bev.y > TSEL) atomicAdd(&sCnt[lr + 8], 1);
        }
    }
    __syncthreads();

    // reserve: one global atomic per (CTA,row)
    if (tid < GM) {
        int c = sCnt[tid];
        sCur[tid] = (c > 0) ? atomicAdd(&g_cnt[m0 + tid], c) : 0;
    }
    __syncthreads();

    // pass 2: write keys at reserved cursor positions
#pragma unroll
    for (int nt = 0; nt < 4; nt++) {
        const int col = n0 + wn32 + nt * 8 + cq;
        const float2 bev = *(const float2*)(be + col);
#pragma unroll
        for (int mt = 0; mt < 4; mt++) {
            const int lr = wm64 + mt * 16 + rq;
            float v[4] = {acc[mt][nt][0] + bev.x, acc[mt][nt][1] + bev.y,
                          acc[mt][nt][2] + bev.x, acc[mt][nt][3] + bev.y};
            const int rr[4] = {lr, lr, lr + 8, lr + 8};
            const int cc[4] = {col, col + 1, col, col + 1};
#pragma unroll
            for (int q = 0; q < 4; q++) {
                if (v[q] > TSEL) {
                    int p = atomicAdd(&sCur[rr[q]], 1);
                    if (p < CAP)
                        g_cand[(size_t)(m0 + rr[q]) * CAP + p] = mk_key(v[q], cc[q]);
                }
            }
        }
    }
}

// ==================== per-row top-64 from candidate list ====================
#define BANDCAP 96

__global__ __launch_bounds__(256)
void k_topk(const float* __restrict__ W_enc, const float* __restrict__ b_enc) {
    const int row = blockIdx.x;
    const int tid = threadIdx.x;
    const int wrp = tid >> 5;
    const int ln = tid & 31;

    __shared__ unsigned long long keys[CAP];
    __shared__ float s_xb[DD];
    __shared__ int s_selIdx[KK];

    int n = g_cnt[row];
    if (n > CAP) n = CAP;
    const int npow = (n <= 512) ? 512 : CAP;

    {
        const unsigned long long* cr = g_cand + (size_t)row * CAP;
        for (int i = tid; i < npow; i += 256) keys[i] = (i < n) ? cr[i] : 0ULL;
        const float4* xb4 = (const float4*)(g_xbar + (size_t)row * DD);
        for (int i = tid; i < DD / 4; i += 256) ((float4*)s_xb)[i] = xb4[i];
    }
    __syncthreads();

    for (int size = 2; size <= npow; size <<= 1) {
        for (int stride = size >> 1; stride > 0; stride >>= 1) {
            for (int i = tid; i < npow; i += 256) {
                int j = i ^ stride;
                if (j > i && j < npow) {
                    bool asc = ((i & size) == 0);
                    unsigned long long x = keys[i], y = keys[j];
                    if ((x > y) == asc) { keys[i] = y; keys[j] = x; }
                }
            }
            __syncthreads();
        }
    }

    __shared__ int s_certain, s_bandN;
    __shared__ int bandIdx[BANDCAP];
    __shared__ double bandD[BANDCAP];
    __shared__ int pickSlot[KK];

    const float v64 = key_val(keys[npow - KK]);
    const float hiv = v64 + DELTA;
    const float lov = v64 - DELTA;
    if (tid == 0) { s_certain = 0; s_bandN = 0; }
    __syncthreads();

    int certLocal = 0;
    for (int i = tid; i < npow; i += 256) {
        unsigned long long kk = keys[i];
        if (kk == 0ULL) continue;
        float v = key_val(kk);
        if (v > hiv) certLocal++;
        else if (v > lov) {
            int p = atomicAdd(&s_bandN, 1);
            if (p < BANDCAP) bandIdx[p] = key_idx(kk);
        }
    }
    {
        int c = certLocal;
#pragma unroll
        for (int o = 16; o > 0; o >>= 1) c += __shfl_down_sync(0xffffffffu, c, o);
        if ((tid & 31) == 0) atomicAdd(&s_certain, c);
    }
    __syncthreads();

    const int certain = s_certain;
    int bandN = s_bandN; if (bandN > BANDCAP) bandN = BANDCAP;
    const int need = KK - certain;

    if (bandN == need || need < 0 || need > bandN) {
        if (tid < KK) {
            int idx = key_idx(keys[npow - 1 - tid]);
            if ((unsigned)idx >= LL) idx = 0;
            s_selIdx[tid] = idx;
        }
        __syncthreads();
    } else {
        if (tid == 0) {
            for (int i = 1; i < bandN; i++) {
                int ki = bandIdx[i];
                int j = i - 1;
                while (j >= 0 && bandIdx[j] > ki) { bandIdx[j + 1] = bandIdx[j]; j--; }
                bandIdx[j + 1] = ki;
            }
        }
        __syncthreads();

        for (int c = wrp; c < bandN; c += 8) {
            const float* wrow = W_enc + (size_t)bandIdx[c] * DD;
            double part = 0.0;
#pragma unroll 4
            for (int t = 0; t < DD / 32; t++)
                part += (double)s_xb[ln + 32 * t] * (double)wrow[ln + 32 * t];
#pragma unroll
            for (int o = 16; o > 0; o >>= 1) part += __shfl_down_sync(0xffffffffu, part, o);
            if (ln == 0) bandD[c] = part + (double)b_enc[bandIdx[c]];
        }
        __syncthreads();

        if (tid == 0) {
            unsigned long long taken[2] = {0ULL, 0ULL};
            for (int p = 0; p < need; p++) {
                int best = -1;
                for (int c = 0; c < bandN; c++) {
                    if ((taken[c >> 6] >> (c & 63)) & 1ULL) continue;
                    if (best < 0 || bandD[c] > bandD[best]) best = c;
                }
                taken[best >> 6] |= 1ULL << (best & 63);
                pickSlot[p] = best;
            }
        }
        __syncthreads();
        if (tid < KK) {
            int idx = (tid < certain) ? key_idx(keys[npow - 1 - tid])
                                      : bandIdx[pickSlot[tid - certain]];
            if ((unsigned)idx >= LL) idx = 0;
            s_selIdx[tid] = idx;
        }
        __syncthreads();
    }

    // exact fp32 recompute of the 64 selected activations
    for (int j = wrp; j < KK; j += 8) {
        const int idx = s_selIdx[j];
        const float* wrow = W_enc + (size_t)idx * DD;
        float part = 0.f;
#pragma unroll 8
        for (int t = 0; t < DD / 32; t++)
            part = fmaf(s_xb[ln + 32 * t], wrow[ln + 32 * t], part);
#pragma unroll
        for (int o = 16; o > 0; o >>= 1) part += __shfl_down_sync(0xffffffffu, part, o);
        if (ln == 0) {
            float v = part + b_enc[idx];
            g_tv[row * KK + j] = v > 0.f ? v : 0.f;
            g_ti[row * KK + j] = idx;
        }
    }
}

// ---------------- f: zero row + scatter relu(vals) ----------------
__global__ void k_scatter(float* __restrict__ f) {
    const int row = blockIdx.x;
    float4* fr = (float4*)(f + (size_t)row * LL);
    for (int i = threadIdx.x; i < LL / 4; i += blockDim.x)
        fr[i] = make_float4(0.f, 0.f, 0.f, 0.f);
    __syncthreads();
    if (threadIdx.x < KK) {
        f[(size_t)row * LL + g_ti[row * KK + threadIdx.x]] = g_tv[row * KK + threadIdx.x];
    }
}

// ---------------- decoder ----------------
__global__ __launch_bounds__(256)
void k_dec(const float* __restrict__ b_dec, float* __restrict__ xhat) {
    const int row = blockIdx.x;
    const int tid = threadIdx.x;
    __shared__ float sv[KK];
    __shared__ int si[KK];
    if (tid < KK) {
        sv[tid] = g_tv[row * KK + tid];
        si[tid] = g_ti[row * KK + tid];
    }
    __syncthreads();
    float4 acc = ((const float4*)b_dec)[tid];
#pragma unroll 4
    for (int j = 0; j < KK; j++) {
        float v = sv[j];
        float4 w = ((const float4*)(g_WdecT + (size_t)si[j] * DD))[tid];
        acc.x += v * w.x; acc.y += v * w.y; acc.z += v * w.z; acc.w += v * w.w;
    }
    ((float4*)(xhat + (size_t)row * DD))[tid] = acc;
}

// ---------------- launcher ----------------
extern "C" void kernel_launch(void* const* d_in, const int* in_sizes, int n_in,
                              void* d_out, int out_size) {
    const float* x     = (const float*)d_in[0];
    const float* W_enc = (const float*)d_in[1];
    const float* b_enc = (const float*)d_in[2];
    const float* W_dec = (const float*)d_in[3];
    const float* b_dec = (const float*)d_in[4];
    float* f    = (float*)d_out;
    float* xhat = f + (size_t)BB * LL;

    cudaFuncSetAttribute(k_gemm, cudaFuncAttributeMaxDynamicSharedMemorySize, GSMEM);

    k_zero_cnt<<<(BB + 255) / 256, 256>>>();
    k_prep_a<<<(BB * DD + 255) / 256, 256>>>(x, b_dec);
    k_prep_b<<<(LL * DD + 255) / 256, 256>>>(W_enc);
    k_transpose<<<dim3(LL / 32, DD / 32), dim3(32, 8)>>>(W_dec);
    k_gemm<<<dim3(BB / GM, LL / GN), 256, GSMEM>>>(b_enc);
    k_topk<<<BB, 256>>>(W_enc, b_enc);
    k_scatter<<<BB, 256>>>(f);
    k_dec<<<BB, 256>>>(b_dec, xhat);
}

// round 11
// speedup vs baseline: 1.0980x; 1.0980x over previous
#include <cuda_runtime.h>
#include <cuda_fp16.h>
#include <cstdint>

// KSparseAutoencoder: B=4096, D=1024, L=16384, K=64, fp32 in/out.
// R11: R6's proven GEMM (2 CTA/SM, 4-stage cp.async, dense write) but the
// activation matrix is stored fp16 (halves C-write + topk-scan traffic).
// Top-64 per row: ladder candidate scan -> bitonic sort -> DELTA=6e-3 band
// (covers fp16 storage + GEMM error) -> fp64 re-rank -> exact fp32 recompute.
// Scatter fused into topk. W_dec transpose overlapped on a side stream.

#define BB 4096
#define DD 1024
#define LL 16384
#define KK 64
#define KTOT 1024
#define DELTA 6e-3f

__device__ float g_xbar[(size_t)BB * DD];        // 16 MB exact
__device__ __half g_A2[(size_t)BB * KTOT];       // 8 MB  xhi
__device__ __half g_B2[(size_t)LL * KTOT];       // 32 MB Whi
__device__ __half g_C16[(size_t)BB * LL];        // 128 MB activations (fp16)
__device__ float g_WdecT[(size_t)LL * DD];       // 64 MB
__device__ float g_tv[BB * KK];
__device__ int   g_ti[BB * KK];

// ==================== helpers ====================
__device__ __forceinline__ uint32_t smem_u32(const void* p) {
    uint32_t a;
    asm("{ .reg .u64 t; cvta.to.shared.u64 t, %1; cvt.u32.u64 %0, t; }" : "=r"(a) : "l"(p));
    return a;
}
__device__ __forceinline__ void cp16(uint32_t dst, const void* src) {
    asm volatile("cp.async.cg.shared.global [%0], [%1], 16;" :: "r"(dst), "l"(src));
}
__device__ __forceinline__ void cp_commit() { asm volatile("cp.async.commit_group;"); }
__device__ __forceinline__ void cp_wait2()  { asm volatile("cp.async.wait_group 2;" ::: "memory"); }

__device__ __forceinline__ void ldsm_x4(uint32_t* r, uint32_t addr) {
    asm volatile("ldmatrix.sync.aligned.m8n8.x4.shared.b16 {%0,%1,%2,%3}, [%4];"
                 : "=r"(r[0]), "=r"(r[1]), "=r"(r[2]), "=r"(r[3]) : "r"(addr));
}
__device__ __forceinline__ void mma16816(float* c, const uint32_t* a, uint32_t b0, uint32_t b1) {
    asm volatile("mma.sync.aligned.m16n8k16.row.col.f32.f16.f16.f32 "
                 "{%0,%1,%2,%3}, {%4,%5,%6,%7}, {%8,%9}, {%0,%1,%2,%3};"
                 : "+f"(c[0]), "+f"(c[1]), "+f"(c[2]), "+f"(c[3])
                 : "r"(a[0]), "r"(a[1]), "r"(a[2]), "r"(a[3]), "r"(b0), "r"(b1));
}
__device__ __forceinline__ unsigned long long mk_key(float v, int i) {
    unsigned u = __float_as_uint(v);
    u = (u & 0x80000000u) ? ~u : (u | 0x80000000u);
    return ((unsigned long long)u << 32) | (unsigned long long)(0xFFFFFFFFu - (unsigned)i);
}
__device__ __forceinline__ float key_val(unsigned long long kk) {
    unsigned u = (unsigned)(kk >> 32);
    unsigned bits = (u & 0x80000000u) ? (u & 0x7FFFFFFFu) : ~u;
    return __uint_as_float(bits);
}
__device__ __forceinline__ int key_idx(unsigned long long kk) {
    return (int)(0xFFFFFFFFu - (unsigned)(kk & 0xFFFFFFFFu));
}

// ==================== prep kernels ====================
__global__ void k_prep_a(const float* __restrict__ x, const float* __restrict__ bd) {
    int i = blockIdx.x * blockDim.x + threadIdx.x;
    if (i >= BB * DD) return;
    int d = i & (DD - 1);
    float xb = x[i] - bd[d];
    g_xbar[i] = xb;
    g_A2[i] = __float2half_rn(xb);
}

__global__ void k_prep_b(const float* __restrict__ W) {
    int i = blockIdx.x * blockDim.x + threadIdx.x;
    if (i >= LL * DD) return;
    g_B2[i] = __float2half_rn(W[i]);
}

// ---------------- transpose W_dec [D][L] -> WdecT [L][D] ----------------
__global__ void k_transpose(const float* __restrict__ W) {
    __shared__ float tile[32][33];
    int lx = blockIdx.x * 32 + threadIdx.x;
    int dy = blockIdx.y * 32 + threadIdx.y;
#pragma unroll
    for (int j = 0; j < 32; j += 8)
        tile[threadIdx.y + j][threadIdx.x] = W[(size_t)(dy + j) * LL + lx];
    __syncthreads();
    int dx = blockIdx.y * 32 + threadIdx.x;
    int ly = blockIdx.x * 32 + threadIdx.y;
#pragma unroll
    for (int j = 0; j < 32; j += 8)
        g_WdecT[(size_t)(ly + j) * DD + dx] = tile[threadIdx.x][threadIdx.y + j];
}

// ==================== fp16 mma.sync GEMM (K=1024), fp16 C ====================
#define GM 128
#define GN 128
#define GK 32
#define NSTG 32
#define ROWB 80
#define A_BYTES (GM * ROWB)
#define B_BYTES (GN * ROWB)
#define STG_BYTES (A_BYTES + B_BYTES)
#define NPIPE 4
#define GSMEM (NPIPE * STG_BYTES)     // 81920

__global__ __launch_bounds__(256, 2)
void k_gemm(const float* __restrict__ be) {
    extern __shared__ __align__(128) char smem[];
    const uint32_t sb = smem_u32(smem);
    const int tid = threadIdx.x;
    const int lane = tid & 31;
    const int wid = tid >> 5;
    const int wm = wid >> 2;
    const int wn = wid & 3;
    const int m0 = blockIdx.x * GM;
    const int n0 = blockIdx.y * GN;

    const __half* Ag = g_A2 + (size_t)m0 * KTOT;
    const __half* Bg = g_B2 + (size_t)n0 * KTOT;

    const int lrow = tid >> 1;
    const int lseg2 = (tid & 1) * 2;
    auto load_stage = [&](int s, int buf) {
        uint32_t ab = sb + buf * STG_BYTES;
        uint32_t bb = ab + A_BYTES;
        const __half* Ak = Ag + s * GK;
        const __half* Bk = Bg + s * GK;
#pragma unroll
        for (int q = 0; q < 2; q++) {
            int seg = lseg2 + q;
            cp16(ab + lrow * ROWB + seg * 16, Ak + (size_t)lrow * KTOT + seg * 8);
            cp16(bb + lrow * ROWB + seg * 16, Bk + (size_t)lrow * KTOT + seg * 8);
        }
        cp_commit();
    };

    float acc[4][4][4];
#pragma unroll
    for (int i = 0; i < 4; i++)
#pragma unroll
        for (int j = 0; j < 4; j++)
#pragma unroll
            for (int q = 0; q < 4; q++) acc[i][j][q] = 0.f;

    load_stage(0, 0);
    load_stage(1, 1);
    load_stage(2, 2);

    const int wm64 = wm * 64;
    const int wn32 = wn * 32;
    const uint32_t a_sub = (uint32_t)(wm64 + (lane & 15)) * ROWB + (((lane >> 4) << 3) << 1);
    const uint32_t b_sub = (uint32_t)(wn32 + (lane & 7) + ((lane & 16) >> 1)) * ROWB
                           + ((lane & 8) << 1);

    for (int s = 0; s < NSTG; s++) {
        const int buf = s & (NPIPE - 1);
        cp_wait2();
        __syncthreads();
        if (s + 3 < NSTG) load_stage(s + 3, (s + 3) & (NPIPE - 1));

        uint32_t ab = sb + buf * STG_BYTES;
        uint32_t bb = ab + A_BYTES;
#pragma unroll
        for (int ks = 0; ks < 2; ks++) {
            const uint32_t k0b = ks * 32;
            uint32_t ra[4][4], rb[2][4];
#pragma unroll
            for (int mt = 0; mt < 4; mt++)
                ldsm_x4(ra[mt], ab + a_sub + (uint32_t)(mt * 16) * ROWB + k0b);
#pragma unroll
            for (int g = 0; g < 2; g++)
                ldsm_x4(rb[g], bb + b_sub + (uint32_t)(g * 16) * ROWB + k0b);
#pragma unroll
            for (int mt = 0; mt < 4; mt++)
#pragma unroll
                for (int nt = 0; nt < 4; nt++)
                    mma16816(acc[mt][nt], ra[mt], rb[nt >> 1][(nt & 1) * 2],
                             rb[nt >> 1][(nt & 1) * 2 + 1]);
        }
    }

    // epilogue: + b_enc, store fp16
    const int cq = (lane & 3) * 2;
    const int rq = lane >> 2;
#pragma unroll
    for (int nt = 0; nt < 4; nt++) {
        const int col = n0 + wn32 + nt * 8 + cq;
        const float2 bev = *(const float2*)(be + col);
#pragma unroll
        for (int mt = 0; mt < 4; mt++) {
            const int row = m0 + wm64 + mt * 16 + rq;
            __half2 h0 = __floats2half2_rn(acc[mt][nt][0] + bev.x, acc[mt][nt][1] + bev.y);
            __half2 h1 = __floats2half2_rn(acc[mt][nt][2] + bev.x, acc[mt][nt][3] + bev.y);
            *(__half2*)(g_C16 + (size_t)row * LL + col) = h0;
            *(__half2*)(g_C16 + (size_t)(row + 8) * LL + col) = h1;
        }
    }
}

// ==================== per-row top-64 + exact rescue + fused scatter ====================
#define NCAND 1024
#define BANDCAP 96

__global__ __launch_bounds__(256)
void k_topk(float* __restrict__ f, const float* __restrict__ W_enc,
            const float* __restrict__ b_enc) {
    const int row = blockIdx.x;
    const int tid = threadIdx.x;
    const int wrp = tid >> 5;
    const int ln = tid & 31;
    const __half* rh = g_C16 + (size_t)row * LL;
    const uint4* r8 = (const uint4*)rh;   // 8 halves per uint4

    __shared__ unsigned long long keys[NCAND];
    __shared__ float s_xb[DD];
    __shared__ int s_selIdx[KK];
    __shared__ float s_selVal[KK];
    __shared__ int s_n;

    const float ladder[8] = {3.4f, 2.8f, 2.3f, 2.0f, 1.65f, 1.2f, 0.6f, -1e30f};
    int li = 3;
    float Tused = ladder[li];
    int n = 0;
    for (int attempt = 0; attempt < 8; attempt++) {
        if (tid == 0) s_n = 0;
        __syncthreads();
        const float T = ladder[li];
        for (int i = tid; i < LL / 8; i += 256) {
            uint4 raw = r8[i];
            int base = i * 8;
            float2 p0 = __half22float2(*(__half2*)&raw.x);
            float2 p1 = __half22float2(*(__half2*)&raw.y);
            float2 p2 = __half22float2(*(__half2*)&raw.z);
            float2 p3 = __half22float2(*(__half2*)&raw.w);
            float v[8] = {p0.x, p0.y, p1.x, p1.y, p2.x, p2.y, p3.x, p3.y};
#pragma unroll
            for (int q = 0; q < 8; q++) {
                if (v[q] > T) {
                    int p = atomicAdd(&s_n, 1);
                    if (p < NCAND) keys[p] = mk_key(v[q], base + q);
                }
            }
        }
        __syncthreads();
        n = s_n;
        Tused = T;
        bool ok = (n >= KK && n <= NCAND);
        if (ok) break;
        if (n > NCAND) { if (li > 0) li--; else break; }
        else           { if (li < 7) li++; else break; }
        __syncthreads();
    }
    if (n > NCAND) n = NCAND;
    const int npow = (n <= 512) ? 512 : NCAND;
    for (int i = n + tid; i < npow; i += 256) keys[i] = 0ULL;

    {
        const float4* xb4 = (const float4*)(g_xbar + (size_t)row * DD);
        for (int i = tid; i < DD / 4; i += 256) ((float4*)s_xb)[i] = xb4[i];
    }
    __syncthreads();

    for (int size = 2; size <= npow; size <<= 1) {
        for (int stride = size >> 1; stride > 0; stride >>= 1) {
            for (int i = tid; i < npow; i += 256) {
                int j = i ^ stride;
                if (j > i && j < npow) {
                    bool asc = ((i & size) == 0);
                    unsigned long long x = keys[i], y = keys[j];
                    if ((x > y) == asc) { keys[i] = y; keys[j] = x; }
                }
            }
            __syncthreads();
        }
    }

    __shared__ int s_certain, s_bandN;
    __shared__ int bandIdx[BANDCAP];
    __shared__ double bandD[BANDCAP];
    __shared__ int pickSlot[KK];

    const float v64 = key_val(keys[npow - KK]);
    const float hiv = v64 + DELTA;
    const float lov = v64 - DELTA;
    if (tid == 0) { s_certain = 0; s_bandN = 0; }
    __syncthreads();

    int certLocal = 0;
    if (lov > Tused) {
        for (int i = tid; i < npow; i += 256) {
            unsigned long long kk = keys[i];
            if (kk == 0ULL) continue;
            float v = key_val(kk);
            if (v > hiv) certLocal++;
            else if (v > lov) {
                int p = atomicAdd(&s_bandN, 1);
                if (p < BANDCAP) bandIdx[p] = key_idx(kk);
            }
        }
    } else {
        for (int i = tid; i < LL; i += 256) {
            float v = __half2float(rh[i]);
            if (v > hiv) certLocal++;
            else if (v > lov) {
                int p = atomicAdd(&s_bandN, 1);
                if (p < BANDCAP) bandIdx[p] = i;
            }
        }
    }
    {
        int c = certLocal;
#pragma unroll
        for (int o = 16; o > 0; o >>= 1) c += __shfl_down_sync(0xffffffffu, c, o);
        if ((tid & 31) == 0) atomicAdd(&s_certain, c);
    }
    __syncthreads();

    const int certain = s_certain;
    int bandN = s_bandN; if (bandN > BANDCAP) bandN = BANDCAP;
    const int need = KK - certain;

    if (bandN == need || need < 0 || need > bandN) {
        if (tid < KK) {
            int idx = key_idx(keys[npow - 1 - tid]);
            if ((unsigned)idx >= LL) idx = 0;
            s_selIdx[tid] = idx;
        }
        __syncthreads();
    } else {
        if (tid == 0) {
            for (int i = 1; i < bandN; i++) {
                int ki = bandIdx[i];
                int j = i - 1;
                while (j >= 0 && bandIdx[j] > ki) { bandIdx[j + 1] = bandIdx[j]; j--; }
                bandIdx[j + 1] = ki;
            }
        }
        __syncthreads();

        for (int c = wrp; c < bandN; c += 8) {
            const float* wrow = W_enc + (size_t)bandIdx[c] * DD;
            double part = 0.0;
#pragma unroll 4
            for (int t = 0; t < DD / 32; t++)
                part += (double)s_xb[ln + 32 * t] * (double)wrow[ln + 32 * t];
#pragma unroll
            for (int o = 16; o > 0; o >>= 1) part += __shfl_down_sync(0xffffffffu, part, o);
            if (ln == 0) bandD[c] = part + (double)b_enc[bandIdx[c]];
        }
        __syncthreads();

        if (tid == 0) {
            unsigned long long taken[2] = {0ULL, 0ULL};
            for (int p = 0; p < need; p++) {
                int best = -1;
                for (int c = 0; c < bandN; c++) {
                    if ((taken[c >> 6] >> (c & 63)) & 1ULL) continue;
                    if (best < 0 || bandD[c] > bandD[best]) best = c;
                }
                taken[best >> 6] |= 1ULL << (best & 63);
                pickSlot[p] = best;
            }
        }
        __syncthreads();
        if (tid < KK) {
            int idx = (tid < certain) ? key_idx(keys[npow - 1 - tid])
                                      : bandIdx[pickSlot[tid - certain]];
            if ((unsigned)idx >= LL) idx = 0;
            s_selIdx[tid] = idx;
        }
        __syncthreads();
    }

    // exact fp32 recompute of the 64 selected activations
    for (int j = wrp; j < KK; j += 8) {
        const int idx = s_selIdx[j];
        const float* wrow = W_enc + (size_t)idx * DD;
        float part = 0.f;
#pragma unroll 8
        for (int t = 0; t < DD / 32; t++)
            part = fmaf(s_xb[ln + 32 * t], wrow[ln + 32 * t], part);
#pragma unroll
        for (int o = 16; o > 0; o >>= 1) part += __shfl_down_sync(0xffffffffu, part, o);
        if (ln == 0) {
            float v = part + b_enc[idx];
            float rv = v > 0.f ? v : 0.f;
            s_selVal[j] = rv;
            g_tv[row * KK + j] = rv;
            g_ti[row * KK + j] = idx;
        }
    }
    __syncthreads();

    // fused scatter: zero the output row, write the 64 sparse values
    float* fr = f + (size_t)row * LL;
    for (int i = tid; i < LL / 4; i += 256)
        ((float4*)fr)[i] = make_float4(0.f, 0.f, 0.f, 0.f);
    __syncthreads();
    if (tid < KK)
        fr[s_selIdx[tid]] = s_selVal[tid];
}

// ---------------- decoder ----------------
__global__ __launch_bounds__(256)
void k_dec(const float* __restrict__ b_dec, float* __restrict__ xhat) {
    const int row = blockIdx.x;
    const int tid = threadIdx.x;
    __shared__ float sv[KK];
    __shared__ int si[KK];
    if (tid < KK) {
        sv[tid] = g_tv[row * KK + tid];
        si[tid] = g_ti[row * KK + tid];
    }
    __syncthreads();
    float4 acc = ((const float4*)b_dec)[tid];
#pragma unroll 4
    for (int j = 0; j < KK; j++) {
        float v = sv[j];
        float4 w = ((const float4*)(g_WdecT + (size_t)si[j] * DD))[tid];
        acc.x += v * w.x; acc.y += v * w.y; acc.z += v * w.z; acc.w += v * w.w;
    }
    ((float4*)(xhat + (size_t)row * DD))[tid] = acc;
}

// ---------------- launcher ----------------
extern "C" void kernel_launch(void* const* d_in, const int* in_sizes, int n_in,
                              void* d_out, int out_size) {
    const float* x     = (const float*)d_in[0];
    const float* W_enc = (const float*)d_in[1];
    const float* b_enc = (const float*)d_in[2];
    const float* W_dec = (const float*)d_in[3];
    const float* b_dec = (const float*)d_in[4];
    float* f    = (float*)d_out;
    float* xhat = f + (size_t)BB * LL;

    static cudaStream_t s_side = nullptr;
    static cudaEvent_t ev_fork = nullptr, ev_join = nullptr;
    if (s_side == nullptr) {
        cudaStreamCreateWithFlags(&s_side, cudaStreamNonBlocking);
        cudaEventCreateWithFlags(&ev_fork, cudaEventDisableTiming);
        cudaEventCreateWithFlags(&ev_join, cudaEventDisableTiming);
        cudaFuncSetAttribute(k_gemm, cudaFuncAttributeMaxDynamicSharedMemorySize, GSMEM);
    }

    // fork: transpose (only needed by k_dec) runs on the side stream
    cudaEventRecord(ev_fork, 0);
    cudaStreamWaitEvent(s_side, ev_fork, 0);
    k_transpose<<<dim3(LL / 32, DD / 32), dim3(32, 8), 0, s_side>>>(W_dec);
    cudaEventRecord(ev_join, s_side);

    k_prep_a<<<(BB * DD + 255) / 256, 256>>>(x, b_dec);
    k_prep_b<<<(LL * DD + 255) / 256, 256>>>(W_enc);
    k_gemm<<<dim3(BB / GM, LL / GN), 256, GSMEM>>>(b_enc);
    k_topk<<<BB, 256>>>(f, W_enc, b_enc);

    // join before decoder (needs WdecT)
    cudaStreamWaitEvent(0, ev_join, 0);
    k_dec<<<BB, 256>>>(b_dec, xhat);
}

// round 15
// speedup vs baseline: 1.1086x; 1.0096x over previous
#include <cuda_runtime.h>
#include <cuda_fp16.h>
#include <cstdint>

// KSparseAutoencoder: B=4096, D=1024, L=16384, K=64, fp32 in/out.
// R12: R11's GEMM (unchanged, HMMA-issue-bound floor ~477us). Non-GEMM path
// restructured: f zeroed by async memset overlapped with the GEMM; decoder
// fused into the topk kernel (reads fp16 WdecT, halving its L2 traffic).

#define BB 4096
#define DD 1024
#define LL 16384
#define KK 64
#define KTOT 1024
#define DELTA 6e-3f

__device__ float g_xbar[(size_t)BB * DD];        // 16 MB exact
__device__ __half g_A2[(size_t)BB * KTOT];       // 8 MB  xhi
__device__ __half g_B2[(size_t)LL * KTOT];       // 32 MB Whi
__device__ __half g_C16[(size_t)BB * LL];        // 128 MB activations (fp16)
__device__ __half g_WdecT16[(size_t)LL * DD];    // 32 MB fp16 transposed W_dec

// ==================== helpers ====================
__device__ __forceinline__ uint32_t smem_u32(const void* p) {
    uint32_t a;
    asm("{ .reg .u64 t; cvta.to.shared.u64 t, %1; cvt.u32.u64 %0, t; }" : "=r"(a) : "l"(p));
    return a;
}
__device__ __forceinline__ void cp16(uint32_t dst, const void* src) {
    asm volatile("cp.async.cg.shared.global [%0], [%1], 16;" :: "r"(dst), "l"(src));
}
__device__ __forceinline__ void cp_commit() { asm volatile("cp.async.commit_group;"); }
__device__ __forceinline__ void cp_wait2()  { asm volatile("cp.async.wait_group 2;" ::: "memory"); }

__device__ __forceinline__ void ldsm_x4(uint32_t* r, uint32_t addr) {
    asm volatile("ldmatrix.sync.aligned.m8n8.x4.shared.b16 {%0,%1,%2,%3}, [%4];"
                 : "=r"(r[0]), "=r"(r[1]), "=r"(r[2]), "=r"(r[3]) : "r"(addr));
}
__device__ __forceinline__ void mma16816(float* c, const uint32_t* a, uint32_t b0, uint32_t b1) {
    asm volatile("mma.sync.aligned.m16n8k16.row.col.f32.f16.f16.f32 "
                 "{%0,%1,%2,%3}, {%4,%5,%6,%7}, {%8,%9}, {%0,%1,%2,%3};"
                 : "+f"(c[0]), "+f"(c[1]), "+f"(c[2]), "+f"(c[3])
                 : "r"(a[0]), "r"(a[1]), "r"(a[2]), "r"(a[3]), "r"(b0), "r"(b1));
}
__device__ __forceinline__ unsigned long long mk_key(float v, int i) {
    unsigned u = __float_as_uint(v);
    u = (u & 0x80000000u) ? ~u : (u | 0x80000000u);
    return ((unsigned long long)u << 32) | (unsigned long long)(0xFFFFFFFFu - (unsigned)i);
}
__device__ __forceinline__ float key_val(unsigned long long kk) {
    unsigned u = (unsigned)(kk >> 32);
    unsigned bits = (u & 0x80000000u) ? (u & 0x7FFFFFFFu) : ~u;
    return __uint_as_float(bits);
}
__device__ __forceinline__ int key_idx(unsigned long long kk) {
    return (int)(0xFFFFFFFFu - (unsigned)(kk & 0xFFFFFFFFu));
}

// ==================== prep kernels ====================
__global__ void k_prep_a(const float* __restrict__ x, const float* __restrict__ bd) {
    int i = blockIdx.x * blockDim.x + threadIdx.x;
    if (i >= BB * DD) return;
    int d = i & (DD - 1);
    float xb = x[i] - bd[d];
    g_xbar[i] = xb;
    g_A2[i] = __float2half_rn(xb);
}

__global__ void k_prep_b(const float* __restrict__ W) {
    int i = blockIdx.x * blockDim.x + threadIdx.x;
    if (i >= LL * DD) return;
    g_B2[i] = __float2half_rn(W[i]);
}

// ---------------- transpose W_dec [D][L] -> WdecT16 [L][D] (fp16) ----------------
__global__ void k_transpose(const float* __restrict__ W) {
    __shared__ float tile[32][33];
    int lx = blockIdx.x * 32 + threadIdx.x;
    int dy = blockIdx.y * 32 + threadIdx.y;
#pragma unroll
    for (int j = 0; j < 32; j += 8)
        tile[threadIdx.y + j][threadIdx.x] = W[(size_t)(dy + j) * LL + lx];
    __syncthreads();
    int dx = blockIdx.y * 32 + threadIdx.x;
    int ly = blockIdx.x * 32 + threadIdx.y;
#pragma unroll
    for (int j = 0; j < 32; j += 8)
        g_WdecT16[(size_t)(ly + j) * DD + dx] = __float2half_rn(tile[threadIdx.x][threadIdx.y + j]);
}

// ==================== fp16 mma.sync GEMM (K=1024), fp16 C ====================
#define GM 128
#define GN 128
#define GK 32
#define NSTG 32
#define ROWB 80
#define A_BYTES (GM * ROWB)
#define B_BYTES (GN * ROWB)
#define STG_BYTES (A_BYTES + B_BYTES)
#define NPIPE 4
#define GSMEM (NPIPE * STG_BYTES)     // 81920

__global__ __launch_bounds__(256, 2)
void k_gemm(const float* __restrict__ be) {
    extern __shared__ __align__(128) char smem[];
    const uint32_t sb = smem_u32(smem);
    const int tid = threadIdx.x;
    const int lane = tid & 31;
    const int wid = tid >> 5;
    const int wm = wid >> 2;
    const int wn = wid & 3;
    const int m0 = blockIdx.x * GM;
    const int n0 = blockIdx.y * GN;

    const __half* Ag = g_A2 + (size_t)m0 * KTOT;
    const __half* Bg = g_B2 + (size_t)n0 * KTOT;

    const int lrow = tid >> 1;
    const int lseg2 = (tid & 1) * 2;
    auto load_stage = [&](int s, int buf) {
        uint32_t ab = sb + buf * STG_BYTES;
        uint32_t bb = ab + A_BYTES;
        const __half* Ak = Ag + s * GK;
        const __half* Bk = Bg + s * GK;
#pragma unroll
        for (int q = 0; q < 2; q++) {
            int seg = lseg2 + q;
            cp16(ab + lrow * ROWB + seg * 16, Ak + (size_t)lrow * KTOT + seg * 8);
            cp16(bb + lrow * ROWB + seg * 16, Bk + (size_t)lrow * KTOT + seg * 8);
        }
        cp_commit();
    };

    float acc[4][4][4];
#pragma unroll
    for (int i = 0; i < 4; i++)
#pragma unroll
        for (int j = 0; j < 4; j++)
#pragma unroll
            for (int q = 0; q < 4; q++) acc[i][j][q] = 0.f;

    load_stage(0, 0);
    load_stage(1, 1);
    load_stage(2, 2);

    const int wm64 = wm * 64;
    const int wn32 = wn * 32;
    const uint32_t a_sub = (uint32_t)(wm64 + (lane & 15)) * ROWB + (((lane >> 4) << 3) << 1);
    const uint32_t b_sub = (uint32_t)(wn32 + (lane & 7) + ((lane & 16) >> 1)) * ROWB
                           + ((lane & 8) << 1);

    for (int s = 0; s < NSTG; s++) {
        const int buf = s & (NPIPE - 1);
        cp_wait2();
        __syncthreads();
        if (s + 3 < NSTG) load_stage(s + 3, (s + 3) & (NPIPE - 1));

        uint32_t ab = sb + buf * STG_BYTES;
        uint32_t bb = ab + A_BYTES;
#pragma unroll
        for (int ks = 0; ks < 2; ks++) {
            const uint32_t k0b = ks * 32;
            uint32_t ra[4][4], rb[2][4];
#pragma unroll
            for (int mt = 0; mt < 4; mt++)
                ldsm_x4(ra[mt], ab + a_sub + (uint32_t)(mt * 16) * ROWB + k0b);
#pragma unroll
            for (int g = 0; g < 2; g++)
                ldsm_x4(rb[g], bb + b_sub + (uint32_t)(g * 16) * ROWB + k0b);
#pragma unroll
            for (int mt = 0; mt < 4; mt++)
#pragma unroll
                for (int nt = 0; nt < 4; nt++)
                    mma16816(acc[mt][nt], ra[mt], rb[nt >> 1][(nt & 1) * 2],
                             rb[nt >> 1][(nt & 1) * 2 + 1]);
        }
    }

    // epilogue: + b_enc, store fp16
    const int cq = (lane & 3) * 2;
    const int rq = lane >> 2;
#pragma unroll
    for (int nt = 0; nt < 4; nt++) {
        const int col = n0 + wn32 + nt * 8 + cq;
        const float2 bev = *(const float2*)(be + col);
#pragma unroll
        for (int mt = 0; mt < 4; mt++) {
            const int row = m0 + wm64 + mt * 16 + rq;
            __half2 h0 = __floats2half2_rn(acc[mt][nt][0] + bev.x, acc[mt][nt][1] + bev.y);
            __half2 h1 = __floats2half2_rn(acc[mt][nt][2] + bev.x, acc[mt][nt][3] + bev.y);
            *(__half2*)(g_C16 + (size_t)row * LL + col) = h0;
            *(__half2*)(g_C16 + (size_t)(row + 8) * LL + col) = h1;
        }
    }
}

// ==================== per-row top-64 + exact rescue + scatter + decoder ====================
#define NCAND 1024
#define BANDCAP 96

__global__ __launch_bounds__(256)
void k_topk(float* __restrict__ f, float* __restrict__ xhat,
            const float* __restrict__ W_enc, const float* __restrict__ b_enc,
            const float* __restrict__ b_dec) {
    const int row = blockIdx.x;
    const int tid = threadIdx.x;
    const int wrp = tid >> 5;
    const int ln = tid & 31;
    const __half* rh = g_C16 + (size_t)row * LL;
    const uint4* r8 = (const uint4*)rh;

    __shared__ unsigned long long keys[NCAND];
    __shared__ float s_xb[DD];
    __shared__ int s_selIdx[KK];
    __shared__ float s_selVal[KK];
    __shared__ int s_n;

    const float ladder[8] = {3.4f, 2.8f, 2.3f, 2.0f, 1.65f, 1.2f, 0.6f, -1e30f};
    int li = 3;
    float Tused = ladder[li];
    int n = 0;
    for (int attempt = 0; attempt < 8; attempt++) {
        if (tid == 0) s_n = 0;
        __syncthreads();
        const float T = ladder[li];
        for (int i = tid; i < LL / 8; i += 256) {
            uint4 raw = r8[i];
            int base = i * 8;
            float2 p0 = __half22float2(*(__half2*)&raw.x);
            float2 p1 = __half22float2(*(__half2*)&raw.y);
            float2 p2 = __half22float2(*(__half2*)&raw.z);
            float2 p3 = __half22float2(*(__half2*)&raw.w);
            float v[8] = {p0.x, p0.y, p1.x, p1.y, p2.x, p2.y, p3.x, p3.y};
#pragma unroll
            for (int q = 0; q < 8; q++) {
                if (v[q] > T) {
                    int p = atomicAdd(&s_n, 1);
                    if (p < NCAND) keys[p] = mk_key(v[q], base + q);
                }
            }
        }
        __syncthreads();
        n = s_n;
        Tused = T;
        bool ok = (n >= KK && n <= NCAND);
        if (ok) break;
        if (n > NCAND) { if (li > 0) li--; else break; }
        else           { if (li < 7) li++; else break; }
        __syncthreads();
    }
    if (n > NCAND) n = NCAND;
    const int npow = (n <= 512) ? 512 : NCAND;
    for (int i = n + tid; i < npow; i += 256) keys[i] = 0ULL;

    {
        const float4* xb4 = (const float4*)(g_xbar + (size_t)row * DD);
        for (int i = tid; i < DD / 4; i += 256) ((float4*)s_xb)[i] = xb4[i];
    }
    __syncthreads();

    for (int size = 2; size <= npow; size <<= 1) {
        for (int stride = size >> 1; stride > 0; stride >>= 1) {
            for (int i = tid; i < npow; i += 256) {
                int j = i ^ stride;
                if (j > i && j < npow) {
                    bool asc = ((i & size) == 0);
                    unsigned long long x = keys[i], y = keys[j];
                    if ((x > y) == asc) { keys[i] = y; keys[j] = x; }
                }
            }
            __syncthreads();
        }
    }

    __shared__ int s_certain, s_bandN;
    __shared__ int bandIdx[BANDCAP];
    __shared__ double bandD[BANDCAP];
    __shared__ int pickSlot[KK];

    const float v64 = key_val(keys[npow - KK]);
    const float hiv = v64 + DELTA;
    const float lov = v64 - DELTA;
    if (tid == 0) { s_certain = 0; s_bandN = 0; }
    __syncthreads();

    int certLocal = 0;
    if (lov > Tused) {
        for (int i = tid; i < npow; i += 256) {
            unsigned long long kk = keys[i];
            if (kk == 0ULL) continue;
            float v = key_val(kk);
            if (v > hiv) certLocal++;
            else if (v > lov) {
                int p = atomicAdd(&s_bandN, 1);
                if (p < BANDCAP) bandIdx[p] = key_idx(kk);
            }
        }
    } else {
        for (int i = tid; i < LL; i += 256) {
            float v = __half2float(rh[i]);
            if (v > hiv) certLocal++;
            else if (v > lov) {
                int p = atomicAdd(&s_bandN, 1);
                if (p < BANDCAP) bandIdx[p] = i;
            }
        }
    }
    {
        int c = certLocal;
#pragma unroll
        for (int o = 16; o > 0; o >>= 1) c += __shfl_down_sync(0xffffffffu, c, o);
        if ((tid & 31) == 0) atomicAdd(&s_certain, c);
    }
    __syncthreads();

    const int certain = s_certain;
    int bandN = s_bandN; if (bandN > BANDCAP) bandN = BANDCAP;
    const int need = KK - certain;

    if (bandN == need || need < 0 || need > bandN) {
        if (tid < KK) {
            int idx = key_idx(keys[npow - 1 - tid]);
            if ((unsigned)idx >= LL) idx = 0;
            s_selIdx[tid] = idx;
        }
        __syncthreads();
    } else {
        if (tid == 0) {
            for (int i = 1; i < bandN; i++) {
                int ki = bandIdx[i];
                int j = i - 1;
                while (j >= 0 && bandIdx[j] > ki) { bandIdx[j + 1] = bandIdx[j]; j--; }
                bandIdx[j + 1] = ki;
            }
        }
        __syncthreads();

        for (int c = wrp; c < bandN; c += 8) {
            const float* wrow = W_enc + (size_t)bandIdx[c] * DD;
            double part = 0.0;
#pragma unroll 4
            for (int t = 0; t < DD / 32; t++)
                part += (double)s_xb[ln + 32 * t] * (double)wrow[ln + 32 * t];
#pragma unroll
            for (int o = 16; o > 0; o >>= 1) part += __shfl_down_sync(0xffffffffu, part, o);
            if (ln == 0) bandD[c] = part + (double)b_enc[bandIdx[c]];
        }
        __syncthreads();

        if (tid == 0) {
            unsigned long long taken[2] = {0ULL, 0ULL};
            for (int p = 0; p < need; p++) {
                int best = -1;
                for (int c = 0; c < bandN; c++) {
                    if ((taken[c >> 6] >> (c & 63)) & 1ULL) continue;
                    if (best < 0 || bandD[c] > bandD[best]) best = c;
                }
                taken[best >> 6] |= 1ULL << (best & 63);
                pickSlot[p] = best;
            }
        }
        __syncthreads();
        if (tid < KK) {
            int idx = (tid < certain) ? key_idx(keys[npow - 1 - tid])
                                      : bandIdx[pickSlot[tid - certain]];
            if ((unsigned)idx >= LL) idx = 0;
            s_selIdx[tid] = idx;
        }
        __syncthreads();
    }

    // exact fp32 recompute of the 64 selected activations
    for (int j = wrp; j < KK; j += 8) {
        const int idx = s_selIdx[j];
        const float* wrow = W_enc + (size_t)idx * DD;
        float part = 0.f;
#pragma unroll 8
        for (int t = 0; t < DD / 32; t++)
            part = fmaf(s_xb[ln + 32 * t], wrow[ln + 32 * t], part);
#pragma unroll
        for (int o = 16; o > 0; o >>= 1) part += __shfl_down_sync(0xffffffffu, part, o);
        if (ln == 0) {
            float v = part + b_enc[idx];
            s_selVal[j] = v > 0.f ? v : 0.f;
        }
    }
    __syncthreads();

    // scatter into f (f pre-zeroed by async memset during the GEMM)
    if (tid < KK)
        f[(size_t)row * LL + s_selIdx[tid]] = s_selVal[tid];

    // fused decoder: xhat[row] = b_dec + sum_j v_j * WdecT16[idx_j]
    {
        float4 accd = ((const float4*)b_dec)[tid];
#pragma unroll 4
        for (int j = 0; j < KK; j++) {
            const float v = s_selVal[j];
            const uint2 raw = *(const uint2*)(g_WdecT16 + (size_t)s_selIdx[j] * DD + tid * 4);
            float2 w01 = __half22float2(*(const __half2*)&raw.x);
            float2 w23 = __half22float2(*(const __half2*)&raw.y);
            accd.x = fmaf(v, w01.x, accd.x);
            accd.y = fmaf(v, w01.y, accd.y);
            accd.z = fmaf(v, w23.x, accd.z);
            accd.w = fmaf(v, w23.y, accd.w);
        }
        ((float4*)(xhat + (size_t)row * DD))[tid] = accd;
    }
}

// ---------------- launcher ----------------
extern "C" void kernel_launch(void* const* d_in, const int* in_sizes, int n_in,
                              void* d_out, int out_size) {
    const float* x     = (const float*)d_in[0];
    const float* W_enc = (const float*)d_in[1];
    const float* b_enc = (const float*)d_in[2];
    const float* W_dec = (const float*)d_in[3];
    const float* b_dec = (const float*)d_in[4];
    float* f    = (float*)d_out;
    float* xhat = f + (size_t)BB * LL;

    static cudaStream_t s_side = nullptr;
    static cudaEvent_t ev_fork = nullptr, ev_join = nullptr;
    if (s_side == nullptr) {
        cudaStreamCreateWithFlags(&s_side, cudaStreamNonBlocking);
        cudaEventCreateWithFlags(&ev_fork, cudaEventDisableTiming);
        cudaEventCreateWithFlags(&ev_join, cudaEventDisableTiming);
        cudaFuncSetAttribute(k_gemm, cudaFuncAttributeMaxDynamicSharedMemorySize, GSMEM);
    }

    // fork: zero f and transpose W_dec on the side stream, concurrent with
    // prep + GEMM on the main stream (GEMM DRAM utilization is ~3%).
    cudaEventRecord(ev_fork, 0);
    cudaStreamWaitEvent(s_side, ev_fork, 0);
    cudaMemsetAsync(f, 0, (size_t)BB * LL * sizeof(float), s_side);
    k_transpose<<<dim3(LL / 32, DD / 32), dim3(32, 8), 0, s_side>>>(W_dec);
    cudaEventRecord(ev_join, s_side);

    k_prep_a<<<(BB * DD + 255) / 256, 256>>>(x, b_dec);
    k_prep_b<<<(LL * DD + 255) / 256, 256>>>(W_enc);
    k_gemm<<<dim3(BB / GM, LL / GN), 256, GSMEM>>>(b_enc);

    // join: topk needs f zeroed and WdecT16 ready
    cudaStreamWaitEvent(0, ev_join, 0);
    k_topk<<<BB, 256>>>(f, xhat, W_enc, b_enc, b_dec);
}

// round 17
// speedup vs baseline: 1.2202x; 1.1007x over previous
#include <cuda_runtime.h>
#include <cuda_fp16.h>
#include <cstdint>

// KSparseAutoencoder: B=4096, D=1024, L=16384, K=64, fp32 in/out.
// R16: R12 minus the exact fp32 recompute (it gathered ~1GB of W_enc rows).
// f values now come from the fp16-stored GEMM results directly (aggregate
// rel_err ~2.4e-4, under the 1e-3 threshold); selection correctness is still
// guaranteed by the DELTA=6e-3 boundary band with fp64 re-ranking, and band
// picks use their exact fp64 values. xbar is staged only for ambiguous rows.

#define BB 4096
#define DD 1024
#define LL 16384
#define KK 64
#define KTOT 1024
#define DELTA 6e-3f

__device__ float g_xbar[(size_t)BB * DD];        // 16 MB exact
__device__ __half g_A2[(size_t)BB * KTOT];       // 8 MB  xhi
__device__ __half g_B2[(size_t)LL * KTOT];       // 32 MB Whi
__device__ __half g_C16[(size_t)BB * LL];        // 128 MB activations (fp16)
__device__ __half g_WdecT16[(size_t)LL * DD];    // 32 MB fp16 transposed W_dec

// ==================== helpers ====================
__device__ __forceinline__ uint32_t smem_u32(const void* p) {
    uint32_t a;
    asm("{ .reg .u64 t; cvta.to.shared.u64 t, %1; cvt.u32.u64 %0, t; }" : "=r"(a) : "l"(p));
    return a;
}
__device__ __forceinline__ void cp16(uint32_t dst, const void* src) {
    asm volatile("cp.async.cg.shared.global [%0], [%1], 16;" :: "r"(dst), "l"(src));
}
__device__ __forceinline__ void cp_commit() { asm volatile("cp.async.commit_group;"); }
__device__ __forceinline__ void cp_wait2()  { asm volatile("cp.async.wait_group 2;" ::: "memory"); }

__device__ __forceinline__ void ldsm_x4(uint32_t* r, uint32_t addr) {
    asm volatile("ldmatrix.sync.aligned.m8n8.x4.shared.b16 {%0,%1,%2,%3}, [%4];"
                 : "=r"(r[0]), "=r"(r[1]), "=r"(r[2]), "=r"(r[3]) : "r"(addr));
}
__device__ __forceinline__ void mma16816(float* c, const uint32_t* a, uint32_t b0, uint32_t b1) {
    asm volatile("mma.sync.aligned.m16n8k16.row.col.f32.f16.f16.f32 "
                 "{%0,%1,%2,%3}, {%4,%5,%6,%7}, {%8,%9}, {%0,%1,%2,%3};"
                 : "+f"(c[0]), "+f"(c[1]), "+f"(c[2]), "+f"(c[3])
                 : "r"(a[0]), "r"(a[1]), "r"(a[2]), "r"(a[3]), "r"(b0), "r"(b1));
}
__device__ __forceinline__ unsigned long long mk_key(float v, int i) {
    unsigned u = __float_as_uint(v);
    u = (u & 0x80000000u) ? ~u : (u | 0x80000000u);
    return ((unsigned long long)u << 32) | (unsigned long long)(0xFFFFFFFFu - (unsigned)i);
}
__device__ __forceinline__ float key_val(unsigned long long kk) {
    unsigned u = (unsigned)(kk >> 32);
    unsigned bits = (u & 0x80000000u) ? (u & 0x7FFFFFFFu) : ~u;
    return __uint_as_float(bits);
}
__device__ __forceinline__ int key_idx(unsigned long long kk) {
    return (int)(0xFFFFFFFFu - (unsigned)(kk & 0xFFFFFFFFu));
}

// ==================== prep kernels ====================
__global__ void k_prep_a(const float* __restrict__ x, const float* __restrict__ bd) {
    int i = blockIdx.x * blockDim.x + threadIdx.x;
    if (i >= BB * DD) return;
    int d = i & (DD - 1);
    float xb = x[i] - bd[d];
    g_xbar[i] = xb;
    g_A2[i] = __float2half_rn(xb);
}

__global__ void k_prep_b(const float* __restrict__ W) {
    int i = blockIdx.x * blockDim.x + threadIdx.x;
    if (i >= LL * DD) return;
    g_B2[i] = __float2half_rn(W[i]);
}

// ---------------- transpose W_dec [D][L] -> WdecT16 [L][D] (fp16) ----------------
__global__ void k_transpose(const float* __restrict__ W) {
    __shared__ float tile[32][33];
    int lx = blockIdx.x * 32 + threadIdx.x;
    int dy = blockIdx.y * 32 + threadIdx.y;
#pragma unroll
    for (int j = 0; j < 32; j += 8)
        tile[threadIdx.y + j][threadIdx.x] = W[(size_t)(dy + j) * LL + lx];
    __syncthreads();
    int dx = blockIdx.y * 32 + threadIdx.x;
    int ly = blockIdx.x * 32 + threadIdx.y;
#pragma unroll
    for (int j = 0; j < 32; j += 8)
        g_WdecT16[(size_t)(ly + j) * DD + dx] = __float2half_rn(tile[threadIdx.x][threadIdx.y + j]);
}

// ==================== fp16 mma.sync GEMM (K=1024), fp16 C ====================
#define GM 128
#define GN 128
#define GK 32
#define NSTG 32
#define ROWB 80
#define A_BYTES (GM * ROWB)
#define B_BYTES (GN * ROWB)
#define STG_BYTES (A_BYTES + B_BYTES)
#define NPIPE 4
#define GSMEM (NPIPE * STG_BYTES)     // 81920

__global__ __launch_bounds__(256, 2)
void k_gemm(const float* __restrict__ be) {
    extern __shared__ __align__(128) char smem[];
    const uint32_t sb = smem_u32(smem);
    const int tid = threadIdx.x;
    const int lane = tid & 31;
    const int wid = tid >> 5;
    const int wm = wid >> 2;
    const int wn = wid & 3;
    const int m0 = blockIdx.x * GM;
    const int n0 = blockIdx.y * GN;

    const __half* Ag = g_A2 + (size_t)m0 * KTOT;
    const __half* Bg = g_B2 + (size_t)n0 * KTOT;

    const int lrow = tid >> 1;
    const int lseg2 = (tid & 1) * 2;
    auto load_stage = [&](int s, int buf) {
        uint32_t ab = sb + buf * STG_BYTES;
        uint32_t bb = ab + A_BYTES;
        const __half* Ak = Ag + s * GK;
        const __half* Bk = Bg + s * GK;
#pragma unroll
        for (int q = 0; q < 2; q++) {
            int seg = lseg2 + q;
            cp16(ab + lrow * ROWB + seg * 16, Ak + (size_t)lrow * KTOT + seg * 8);
            cp16(bb + lrow * ROWB + seg * 16, Bk + (size_t)lrow * KTOT + seg * 8);
        }
        cp_commit();
    };

    float acc[4][4][4];
#pragma unroll
    for (int i = 0; i < 4; i++)
#pragma unroll
        for (int j = 0; j < 4; j++)
#pragma unroll
            for (int q = 0; q < 4; q++) acc[i][j][q] = 0.f;

    load_stage(0, 0);
    load_stage(1, 1);
    load_stage(2, 2);

    const int wm64 = wm * 64;
    const int wn32 = wn * 32;
    const uint32_t a_sub = (uint32_t)(wm64 + (lane & 15)) * ROWB + (((lane >> 4) << 3) << 1);
    const uint32_t b_sub = (uint32_t)(wn32 + (lane & 7) + ((lane & 16) >> 1)) * ROWB
                           + ((lane & 8) << 1);

    for (int s = 0; s < NSTG; s++) {
        const int buf = s & (NPIPE - 1);
        cp_wait2();
        __syncthreads();
        if (s + 3 < NSTG) load_stage(s + 3, (s + 3) & (NPIPE - 1));

        uint32_t ab = sb + buf * STG_BYTES;
        uint32_t bb = ab + A_BYTES;
#pragma unroll
        for (int ks = 0; ks < 2; ks++) {
            const uint32_t k0b = ks * 32;
            uint32_t ra[4][4], rb[2][4];
#pragma unroll
            for (int mt = 0; mt < 4; mt++)
                ldsm_x4(ra[mt], ab + a_sub + (uint32_t)(mt * 16) * ROWB + k0b);
#pragma unroll
            for (int g = 0; g < 2; g++)
                ldsm_x4(rb[g], bb + b_sub + (uint32_t)(g * 16) * ROWB + k0b);
#pragma unroll
            for (int mt = 0; mt < 4; mt++)
#pragma unroll
                for (int nt = 0; nt < 4; nt++)
                    mma16816(acc[mt][nt], ra[mt], rb[nt >> 1][(nt & 1) * 2],
                             rb[nt >> 1][(nt & 1) * 2 + 1]);
        }
    }

    // epilogue: + b_enc, store fp16
    const int cq = (lane & 3) * 2;
    const int rq = lane >> 2;
#pragma unroll
    for (int nt = 0; nt < 4; nt++) {
        const int col = n0 + wn32 + nt * 8 + cq;
        const float2 bev = *(const float2*)(be + col);
#pragma unroll
        for (int mt = 0; mt < 4; mt++) {
            const int row = m0 + wm64 + mt * 16 + rq;
            __half2 h0 = __floats2half2_rn(acc[mt][nt][0] + bev.x, acc[mt][nt][1] + bev.y);
            __half2 h1 = __floats2half2_rn(acc[mt][nt][2] + bev.x, acc[mt][nt][3] + bev.y);
            *(__half2*)(g_C16 + (size_t)row * LL + col) = h0;
            *(__half2*)(g_C16 + (size_t)(row + 8) * LL + col) = h1;
        }
    }
}

// ==================== per-row top-64 + scatter + decoder ====================
#define NCAND 1024
#define BANDCAP 96

__global__ __launch_bounds__(256)
void k_topk(float* __restrict__ f, float* __restrict__ xhat,
            const float* __restrict__ W_enc, const float* __restrict__ b_enc,
            const float* __restrict__ b_dec) {
    const int row = blockIdx.x;
    const int tid = threadIdx.x;
    const int wrp = tid >> 5;
    const int ln = tid & 31;
    const __half* rh = g_C16 + (size_t)row * LL;
    const uint4* r8 = (const uint4*)rh;

    __shared__ unsigned long long keys[NCAND];
    __shared__ float s_xb[DD];
    __shared__ int s_selIdx[KK];
    __shared__ float s_selVal[KK];
    __shared__ int s_n;

    const float ladder[8] = {3.4f, 2.8f, 2.3f, 2.0f, 1.65f, 1.2f, 0.6f, -1e30f};
    int li = 3;
    float Tused = ladder[li];
    int n = 0;
    for (int attempt = 0; attempt < 8; attempt++) {
        if (tid == 0) s_n = 0;
        __syncthreads();
        const float T = ladder[li];
        for (int i = tid; i < LL / 8; i += 256) {
            uint4 raw = r8[i];
            int base = i * 8;
            float2 p0 = __half22float2(*(__half2*)&raw.x);
            float2 p1 = __half22float2(*(__half2*)&raw.y);
            float2 p2 = __half22float2(*(__half2*)&raw.z);
            float2 p3 = __half22float2(*(__half2*)&raw.w);
            float v[8] = {p0.x, p0.y, p1.x, p1.y, p2.x, p2.y, p3.x, p3.y};
#pragma unroll
            for (int q = 0; q < 8; q++) {
                if (v[q] > T) {
                    int p = atomicAdd(&s_n, 1);
                    if (p < NCAND) keys[p] = mk_key(v[q], base + q);
                }
            }
        }
        __syncthreads();
        n = s_n;
        Tused = T;
        bool ok = (n >= KK && n <= NCAND);
        if (ok) break;
        if (n > NCAND) { if (li > 0) li--; else break; }
        else           { if (li < 7) li++; else break; }
        __syncthreads();
    }
    if (n > NCAND) n = NCAND;
    const int npow = (n <= 512) ? 512 : NCAND;
    for (int i = n + tid; i < npow; i += 256) keys[i] = 0ULL;
    __syncthreads();

    for (int size = 2; size <= npow; size <<= 1) {
        for (int stride = size >> 1; stride > 0; stride >>= 1) {
            for (int i = tid; i < npow; i += 256) {
                int j = i ^ stride;
                if (j > i && j < npow) {
                    bool asc = ((i & size) == 0);
                    unsigned long long x = keys[i], y = keys[j];
                    if ((x > y) == asc) { keys[i] = y; keys[j] = x; }
                }
            }
            __syncthreads();
        }
    }

    __shared__ int s_certain, s_bandN;
    __shared__ int bandIdx[BANDCAP];
    __shared__ double bandD[BANDCAP];
    __shared__ int pickSlot[KK];

    const float v64 = key_val(keys[npow - KK]);
    const float hiv = v64 + DELTA;
    const float lov = v64 - DELTA;
    if (tid == 0) { s_certain = 0; s_bandN = 0; }
    __syncthreads();

    int certLocal = 0;
    if (lov > Tused) {
        for (int i = tid; i < npow; i += 256) {
            unsigned long long kk = keys[i];
            if (kk == 0ULL) continue;
            float v = key_val(kk);
            if (v > hiv) certLocal++;
            else if (v > lov) {
                int p = atomicAdd(&s_bandN, 1);
                if (p < BANDCAP) bandIdx[p] = key_idx(kk);
            }
        }
    } else {
        for (int i = tid; i < LL; i += 256) {
            float v = __half2float(rh[i]);
            if (v > hiv) certLocal++;
            else if (v > lov) {
                int p = atomicAdd(&s_bandN, 1);
                if (p < BANDCAP) bandIdx[p] = i;
            }
        }
    }
    {
        int c = certLocal;
#pragma unroll
        for (int o = 16; o > 0; o >>= 1) c += __shfl_down_sync(0xffffffffu, c, o);
        if ((tid & 31) == 0) atomicAdd(&s_certain, c);
    }
    __syncthreads();

    const int certain = s_certain;
    int bandN = s_bandN; if (bandN > BANDCAP) bandN = BANDCAP;
    const int need = KK - certain;

    if (bandN == need || need < 0 || need > bandN) {
        // unambiguous: take sorted top-64 with their fp16-derived values
        if (tid < KK) {
            unsigned long long kk = keys[npow - 1 - tid];
            int idx = key_idx(kk);
            if ((unsigned)idx >= LL) idx = 0;
            s_selIdx[tid] = idx;
            s_selVal[tid] = fmaxf(key_val(kk), 0.f);
        }
        __syncthreads();
    } else {
        // ambiguous: stage exact xbar row, fp64 re-rank the band
        {
            const float4* xb4 = (const float4*)(g_xbar + (size_t)row * DD);
            for (int i = tid; i < DD / 4; i += 256) ((float4*)s_xb)[i] = xb4[i];
        }
        if (tid == 0) {
            for (int i = 1; i < bandN; i++) {
                int ki = bandIdx[i];
                int j = i - 1;
                while (j >= 0 && bandIdx[j] > ki) { bandIdx[j + 1] = bandIdx[j]; j--; }
                bandIdx[j + 1] = ki;
            }
        }
        __syncthreads();

        for (int c = wrp; c < bandN; c += 8) {
            const float* wrow = W_enc + (size_t)bandIdx[c] * DD;
            double part = 0.0;
#pragma unroll 4
            for (int t = 0; t < DD / 32; t++)
                part += (double)s_xb[ln + 32 * t] * (double)wrow[ln + 32 * t];
#pragma unroll
            for (int o = 16; o > 0; o >>= 1) part += __shfl_down_sync(0xffffffffu, part, o);
            if (ln == 0) bandD[c] = part + (double)b_enc[bandIdx[c]];
        }
        __syncthreads();

        if (tid == 0) {
            unsigned long long taken[2] = {0ULL, 0ULL};
            for (int p = 0; p < need; p++) {
                int best = -1;
                for (int c = 0; c < bandN; c++) {
                    if ((taken[c >> 6] >> (c & 63)) & 1ULL) continue;
                    if (best < 0 || bandD[c] > bandD[best]) best = c;
                }
                taken[best >> 6] |= 1ULL << (best & 63);
                pickSlot[p] = best;
            }
        }
        __syncthreads();
        if (tid < KK) {
            if (tid < certain) {
                unsigned long long kk = keys[npow - 1 - tid];
                int idx = key_idx(kk);
                if ((unsigned)idx >= LL) idx = 0;
                s_selIdx[tid] = idx;
                s_selVal[tid] = fmaxf(key_val(kk), 0.f);
            } else {
                int c = pickSlot[tid - certain];
                s_selIdx[tid] = bandIdx[c];
                s_selVal[tid] = fmaxf((float)bandD[c], 0.f);   // exact for band picks
            }
        }
        __syncthreads();
    }

    // scatter into f (f pre-zeroed by async memset during the GEMM)
    if (tid < KK)
        f[(size_t)row * LL + s_selIdx[tid]] = s_selVal[tid];

    // fused decoder: xhat[row] = b_dec + sum_j v_j * WdecT16[idx_j]
    {
        float4 accd = ((const float4*)b_dec)[tid];
#pragma unroll 4
        for (int j = 0; j < KK; j++) {
            const float v = s_selVal[j];
            const uint2 raw = *(const uint2*)(g_WdecT16 + (size_t)s_selIdx[j] * DD + tid * 4);
            float2 w01 = __half22float2(*(const __half2*)&raw.x);
            float2 w23 = __half22float2(*(const __half2*)&raw.y);
            accd.x = fmaf(v, w01.x, accd.x);
            accd.y = fmaf(v, w01.y, accd.y);
            accd.z = fmaf(v, w23.x, accd.z);
            accd.w = fmaf(v, w23.y, accd.w);
        }
        ((float4*)(xhat + (size_t)row * DD))[tid] = accd;
    }
}

// ---------------- launcher ----------------
extern "C" void kernel_launch(void* const* d_in, const int* in_sizes, int n_in,
                              void* d_out, int out_size) {
    const float* x     = (const float*)d_in[0];
    const float* W_enc = (const float*)d_in[1];
    const float* b_enc = (const float*)d_in[2];
    const float* W_dec = (const float*)d_in[3];
    const float* b_dec = (const float*)d_in[4];
    float* f    = (float*)d_out;
    float* xhat = f + (size_t)BB * LL;

    static cudaStream_t s_side = nullptr;
    static cudaEvent_t ev_fork = nullptr, ev_join = nullptr;
    if (s_side == nullptr) {
        cudaStreamCreateWithFlags(&s_side, cudaStreamNonBlocking);
        cudaEventCreateWithFlags(&ev_fork, cudaEventDisableTiming);
        cudaEventCreateWithFlags(&ev_join, cudaEventDisableTiming);
        cudaFuncSetAttribute(k_gemm, cudaFuncAttributeMaxDynamicSharedMemorySize, GSMEM);
    }

    // fork: zero f + transpose W_dec concurrent with prep + GEMM
    cudaEventRecord(ev_fork, 0);
    cudaStreamWaitEvent(s_side, ev_fork, 0);
    cudaMemsetAsync(f, 0, (size_t)BB * LL * sizeof(float), s_side);
    k_transpose<<<dim3(LL / 32, DD / 32), dim3(32, 8), 0, s_side>>>(W_dec);
    cudaEventRecord(ev_join, s_side);

    k_prep_a<<<(BB * DD + 255) / 256, 256>>>(x, b_dec);
    k_prep_b<<<(LL * DD + 255) / 256, 256>>>(W_enc);
    k_gemm<<<dim3(BB / GM, LL / GN), 256, GSMEM>>>(b_enc);

    // join: topk needs f zeroed and WdecT16 ready
    cudaStreamWaitEvent(0, ev_join, 0);
    k_topk<<<BB, 256>>>(f, xhat, W_enc, b_enc, b_dec);
}